// round 3
// baseline (speedup 1.0000x reference)
#include <cuda_runtime.h>
#include <math.h>

#define Bc 2
#define Sc 2048
#define Dc 1024
#define Hc 16
#define DKc 64
#define BSc (Bc*Sc)   // 4096

// Scratch (no allocations allowed)
__device__ float g_qkv[(size_t)BSc * 3 * Dc];      // [B,S,3,H,DK]
__device__ float g_q[(size_t)Bc*Hc*Sc*DKc];        // [B,H,S,DK]
__device__ float g_k[(size_t)Bc*Hc*Sc*DKc];
__device__ float g_v[(size_t)Bc*Hc*Sc*DKc];
__device__ float g_attn[(size_t)BSc * Dc];         // [B,S,D]

// ---------------------------------------------------------------------------
// Classic 128x128x8 SGEMM, 256 threads, 8x8 per thread. Dims must be
// multiples of 128 (M) / 128 (N) / 8 (K) — true for all uses here.
// ---------------------------------------------------------------------------
__global__ void sgemm_kernel(const float* __restrict__ A,
                             const float* __restrict__ Bm,
                             float* __restrict__ C,
                             int M, int N, int K) {
    __shared__ float As[8 * 132];   // [k][m] with pad 4 -> conflict-free stores
    __shared__ float Bs[8 * 128];   // [k][n]

    const int tid = threadIdx.x;
    const int tx = tid & 15;
    const int ty = tid >> 4;
    const int m0 = blockIdx.y << 7;
    const int n0 = blockIdx.x << 7;

    float acc[8][8];
#pragma unroll
    for (int i = 0; i < 8; i++)
#pragma unroll
        for (int j = 0; j < 8; j++) acc[i][j] = 0.f;

    for (int k0 = 0; k0 < K; k0 += 8) {
#pragma unroll
        for (int i = 0; i < 4; i++) {
            int e = tid + (i << 8);
            int m = e >> 3, kk = e & 7;
            As[kk * 132 + m] = A[(size_t)(m0 + m) * K + k0 + kk];
        }
#pragma unroll
        for (int i = 0; i < 4; i++) {
            int e = tid + (i << 8);
            int kk = e >> 7, n = e & 127;
            Bs[kk * 128 + n] = Bm[(size_t)(k0 + kk) * N + n0 + n];
        }
        __syncthreads();

#pragma unroll
        for (int kk = 0; kk < 8; kk++) {
            float a[8], bb[8];
#pragma unroll
            for (int i = 0; i < 8; i++) a[i] = As[kk * 132 + ty * 8 + i];
#pragma unroll
            for (int j = 0; j < 8; j++) bb[j] = Bs[kk * 128 + tx * 8 + j];
#pragma unroll
            for (int i = 0; i < 8; i++)
#pragma unroll
                for (int j = 0; j < 8; j++) acc[i][j] += a[i] * bb[j];
        }
        __syncthreads();
    }

#pragma unroll
    for (int i = 0; i < 8; i++)
#pragma unroll
        for (int j = 0; j < 8; j++)
            C[(size_t)(m0 + ty * 8 + i) * N + n0 + tx * 8 + j] = acc[i][j];
}

// ---------------------------------------------------------------------------
// RoPE + split heads. qkv: [B,S,3,H,DK]. Writes Q/K/V as [B,H,S,DK].
// Replicates the reference table math in fp32 to minimize divergence.
// ---------------------------------------------------------------------------
__global__ void rope_split_kernel(const float* __restrict__ qkv,
                                  float* __restrict__ Q,
                                  float* __restrict__ Kp,
                                  float* __restrict__ V) {
    int idx = blockIdx.x * blockDim.x + threadIdx.x;  // [b][s][h][d]
    int d = idx & 63;
    int h = (idx >> 6) & (Hc - 1);
    int s = (idx >> 10) & (Sc - 1);
    int b = idx >> 21;

    const float* base = qkv + (size_t)(b * Sc + s) * 3 * Dc + h * DKc;
    float qv = base[d];
    float kv = base[Dc + d];
    float vv = base[2 * Dc + d];

    int d2 = d & 31;
    float invf = 1.0f / powf(10000.0f, (float)d2 * (1.0f / 32.0f));
    float ang = (float)s * invf;
    float sn, c;
    sincosf(ang, &sn, &c);

    int dp = d ^ 32;            // rotate_half partner
    float qp = base[dp];
    float kp = base[Dc + dp];
    float sgn = (d < 32) ? -1.0f : 1.0f;

    float qo = qv * c + sgn * qp * sn;
    float ko = kv * c + sgn * kp * sn;

    size_t o = ((size_t)(b * Hc + h) * Sc + s) * DKc + d;
    Q[o] = qo;
    Kp[o] = ko;
    V[o] = vv;
}

// ---------------------------------------------------------------------------
// Flash attention: 64x64 tiles, online softmax, causal skipping.
// 256 threads; thread (ty,tx) owns a 4x4 micro-tile.
// SMEM: Qs transposed [d][r] pad65, KP union (K^T tile / P tile), Vs [j][dv].
// ---------------------------------------------------------------------------
__global__ void flash_attn_kernel(const float* __restrict__ Q,
                                  const float* __restrict__ K,
                                  const float* __restrict__ V,
                                  float* __restrict__ Out) {
    extern __shared__ float sm[];
    float* Qs  = sm;                 // [64][65] : Qs[d*65 + r]
    float* KP  = sm + 64 * 65;       // Ks_t[d*65 + c]  OR  Ps[r*65 + c]
    float* Vs  = KP + 64 * 65;       // [64][64] : Vs[j*64 + dv]
    float* mS  = Vs + 64 * 64;       // [64]
    float* lS  = mS + 64;            // [64]
    float* corr = lS + 64;           // [64]

    const int tid = threadIdx.x;
    const int tx = tid & 15;
    const int ty = tid >> 4;
    const int bh = blockIdx.x;       // b*H + h
    const int qt = blockIdx.y;
    const int q0 = qt * 64;

    const float* Qb = Q + (size_t)bh * Sc * DKc;
    const float* Kb = K + (size_t)bh * Sc * DKc;
    const float* Vb = V + (size_t)bh * Sc * DKc;

    // Load Q tile (pre-scaled by 1/sqrt(dk))
#pragma unroll
    for (int i = 0; i < 16; i++) {
        int e = tid + i * 256;
        int r = e >> 6, d = e & 63;
        Qs[d * 65 + r] = Qb[(size_t)(q0 + r) * DKc + d] * 0.125f;
    }
    if (tid < 64) { mS[tid] = -INFINITY; lS[tid] = 0.f; }
    __syncthreads();

    float acc[4][4];
#pragma unroll
    for (int i = 0; i < 4; i++)
#pragma unroll
        for (int j = 0; j < 4; j++) acc[i][j] = 0.f;

    const int nkt = qt + 1;          // causal: only key tiles <= query tile
    for (int kt = 0; kt < nkt; kt++) {
        const int k0 = kt * 64;

        // Load K^T tile and V tile
#pragma unroll
        for (int i = 0; i < 16; i++) {
            int e = tid + i * 256;
            int c = e >> 6, d = e & 63;
            KP[d * 65 + c] = Kb[(size_t)(k0 + c) * DKc + d];
        }
#pragma unroll
        for (int i = 0; i < 16; i++) {
            int e = tid + i * 256;
            int j = e >> 6, dv = e & 63;
            Vs[j * 64 + dv] = Vb[(size_t)(k0 + j) * DKc + dv];
        }
        __syncthreads();

        // Scores: S = (Q*scale) @ K^T
        float sreg[4][4];
#pragma unroll
        for (int i = 0; i < 4; i++)
#pragma unroll
            for (int j = 0; j < 4; j++) sreg[i][j] = 0.f;

#pragma unroll
        for (int d = 0; d < 64; d++) {
            float a[4], bb[4];
#pragma unroll
            for (int i = 0; i < 4; i++) a[i] = Qs[d * 65 + ty * 4 + i];
#pragma unroll
            for (int j = 0; j < 4; j++) bb[j] = KP[d * 65 + tx * 4 + j];
#pragma unroll
            for (int i = 0; i < 4; i++)
#pragma unroll
                for (int j = 0; j < 4; j++) sreg[i][j] += a[i] * bb[j];
        }
        __syncthreads();   // all K^T reads done before overwriting KP with P

        // Causal mask (only possible on the diagonal tile) + write raw scores
        const bool diag = (kt == qt);
#pragma unroll
        for (int i = 0; i < 4; i++)
#pragma unroll
            for (int j = 0; j < 4; j++) {
                float sv = sreg[i][j];
                if (diag && (tx * 4 + j > ty * 4 + i)) sv = -INFINITY;
                KP[(ty * 4 + i) * 65 + tx * 4 + j] = sv;
            }
        __syncthreads();

        // Online softmax row statistics (threads 0..63, one per row)
        if (tid < 64) {
            const int r = tid;
            float mold = mS[r];
            float mx = mold;
            for (int c = 0; c < 64; c++) mx = fmaxf(mx, KP[r * 65 + c]);
            float cr = expf(mold - mx);       // 0 on first tile (mold=-inf)
            float sum = 0.f;
            for (int c = 0; c < 64; c++) {
                float p = expf(KP[r * 65 + c] - mx);
                KP[r * 65 + c] = p;
                sum += p;
            }
            lS[r] = lS[r] * cr + sum;
            mS[r] = mx;
            corr[r] = cr;
        }
        __syncthreads();

        // Rescale accumulators and do P @ V
        float cr[4];
#pragma unroll
        for (int i = 0; i < 4; i++) cr[i] = corr[ty * 4 + i];
#pragma unroll
        for (int i = 0; i < 4; i++)
#pragma unroll
            for (int j = 0; j < 4; j++) acc[i][j] *= cr[i];

#pragma unroll 16
        for (int j = 0; j < 64; j++) {
            float a[4], bb[4];
#pragma unroll
            for (int i = 0; i < 4; i++) a[i] = KP[(ty * 4 + i) * 65 + j];
#pragma unroll
            for (int x = 0; x < 4; x++) bb[x] = Vs[j * 64 + tx * 4 + x];
#pragma unroll
            for (int i = 0; i < 4; i++)
#pragma unroll
                for (int x = 0; x < 4; x++) acc[i][x] += a[i] * bb[x];
        }
        __syncthreads();   // protect KP/Vs before next tile's loads
    }

    // Normalize and write out as [B,S,H*DK]
    const int b = bh >> 4;
    const int h = bh & 15;
    float inv[4];
#pragma unroll
    for (int i = 0; i < 4; i++) inv[i] = 1.0f / lS[ty * 4 + i];
#pragma unroll
    for (int i = 0; i < 4; i++)
#pragma unroll
        for (int j = 0; j < 4; j++)
            Out[(size_t)(b * Sc + q0 + ty * 4 + i) * Dc + h * DKc + tx * 4 + j] =
                acc[i][j] * inv[i];
}

// ---------------------------------------------------------------------------
extern "C" void kernel_launch(void* const* d_in, const int* in_sizes, int n_in,
                              void* d_out, int out_size) {
    const float* x    = (const float*)d_in[0];   // [B,S,D]
    const float* Wqkv = (const float*)d_in[1];   // [D, 3D]
    const float* Wo   = (const float*)d_in[2];   // [D, D]
    float* out = (float*)d_out;

    float *qkv, *q, *k, *v, *attn;
    cudaGetSymbolAddress((void**)&qkv,  g_qkv);
    cudaGetSymbolAddress((void**)&q,    g_q);
    cudaGetSymbolAddress((void**)&k,    g_k);
    cudaGetSymbolAddress((void**)&v,    g_v);
    cudaGetSymbolAddress((void**)&attn, g_attn);

    // 1. QKV projection: [4096,1024] @ [1024,3072]
    sgemm_kernel<<<dim3(3 * Dc / 128, BSc / 128), 256>>>(x, Wqkv, qkv, BSc, 3 * Dc, Dc);

    // 2. RoPE + head split
    rope_split_kernel<<<(Bc * Sc * Hc * DKc) / 256, 256>>>(qkv, q, k, v);

    // 3. Causal flash attention
    const int smem = (64 * 65 * 2 + 64 * 64 + 3 * 64) * (int)sizeof(float);  // 50432 B
    cudaFuncSetAttribute(flash_attn_kernel,
                         cudaFuncAttributeMaxDynamicSharedMemorySize, smem);
    flash_attn_kernel<<<dim3(Bc * Hc, Sc / 64), 256, smem>>>(q, k, v, attn);

    // 4. Output projection: [4096,1024] @ [1024,1024]
    sgemm_kernel<<<dim3(Dc / 128, BSc / 128), 256>>>(attn, Wo, out, BSc, Dc, Dc);
}

// round 4
// speedup vs baseline: 1.0462x; 1.0462x over previous
#include <cuda_runtime.h>
#include <math.h>

#define Bc 2
#define Sc 2048
#define Dc 1024
#define Hc 16
#define DKc 64
#define BSc (Bc*Sc)   // 4096

// Scratch (no allocations allowed)
__device__ float g_qkv[(size_t)BSc * 3 * Dc];      // [B,S,3,H,DK]
__device__ float g_q[(size_t)Bc*Hc*Sc*DKc];        // [B,H,S,DK]
__device__ float g_k[(size_t)Bc*Hc*Sc*DKc];
__device__ float g_v[(size_t)Bc*Hc*Sc*DKc];
__device__ float g_attn[(size_t)BSc * Dc];         // [B,S,D]

// ---------------------------------------------------------------------------
// Classic 128x128x8 SGEMM, 256 threads, 8x8 per thread. (unchanged from R2)
// ---------------------------------------------------------------------------
__global__ void sgemm_kernel(const float* __restrict__ A,
                             const float* __restrict__ Bm,
                             float* __restrict__ C,
                             int M, int N, int K) {
    __shared__ float As[8 * 132];
    __shared__ float Bs[8 * 128];

    const int tid = threadIdx.x;
    const int tx = tid & 15;
    const int ty = tid >> 4;
    const int m0 = blockIdx.y << 7;
    const int n0 = blockIdx.x << 7;

    float acc[8][8];
#pragma unroll
    for (int i = 0; i < 8; i++)
#pragma unroll
        for (int j = 0; j < 8; j++) acc[i][j] = 0.f;

    for (int k0 = 0; k0 < K; k0 += 8) {
#pragma unroll
        for (int i = 0; i < 4; i++) {
            int e = tid + (i << 8);
            int m = e >> 3, kk = e & 7;
            As[kk * 132 + m] = A[(size_t)(m0 + m) * K + k0 + kk];
        }
#pragma unroll
        for (int i = 0; i < 4; i++) {
            int e = tid + (i << 8);
            int kk = e >> 7, n = e & 127;
            Bs[kk * 128 + n] = Bm[(size_t)(k0 + kk) * N + n0 + n];
        }
        __syncthreads();

#pragma unroll
        for (int kk = 0; kk < 8; kk++) {
            float a[8], bb[8];
#pragma unroll
            for (int i = 0; i < 8; i++) a[i] = As[kk * 132 + ty * 8 + i];
#pragma unroll
            for (int j = 0; j < 8; j++) bb[j] = Bs[kk * 128 + tx * 8 + j];
#pragma unroll
            for (int i = 0; i < 8; i++)
#pragma unroll
                for (int j = 0; j < 8; j++) acc[i][j] += a[i] * bb[j];
        }
        __syncthreads();
    }

#pragma unroll
    for (int i = 0; i < 8; i++)
#pragma unroll
        for (int j = 0; j < 8; j++)
            C[(size_t)(m0 + ty * 8 + i) * N + n0 + tx * 8 + j] = acc[i][j];
}

// ---------------------------------------------------------------------------
// RoPE + split heads (unchanged)
// ---------------------------------------------------------------------------
__global__ void rope_split_kernel(const float* __restrict__ qkv,
                                  float* __restrict__ Q,
                                  float* __restrict__ Kp,
                                  float* __restrict__ V) {
    int idx = blockIdx.x * blockDim.x + threadIdx.x;  // [b][s][h][d]
    int d = idx & 63;
    int h = (idx >> 6) & (Hc - 1);
    int s = (idx >> 10) & (Sc - 1);
    int b = idx >> 21;

    const float* base = qkv + (size_t)(b * Sc + s) * 3 * Dc + h * DKc;
    float qv = base[d];
    float kv = base[Dc + d];
    float vv = base[2 * Dc + d];

    int d2 = d & 31;
    float invf = 1.0f / powf(10000.0f, (float)d2 * (1.0f / 32.0f));
    float ang = (float)s * invf;
    float sn, c;
    sincosf(ang, &sn, &c);

    int dp = d ^ 32;            // rotate_half partner
    float qp = base[dp];
    float kp = base[Dc + dp];
    float sgn = (d < 32) ? -1.0f : 1.0f;

    float qo = qv * c + sgn * qp * sn;
    float ko = kv * c + sgn * kp * sn;

    size_t o = ((size_t)(b * Hc + h) * Sc + s) * DKc + d;
    Q[o] = qo;
    Kp[o] = ko;
    V[o] = vv;
}

// ---------------------------------------------------------------------------
// Flash attention v2: 64x64 tiles, register softmax + shuffle reductions,
// float4 SMEM traffic everywhere, 3 syncthreads per tile.
// Thread (ty,tx) owns rows ty*4+i, cols tx*4+j. Row group = 16 lanes (tx).
// ---------------------------------------------------------------------------
#define FS 68   // padded row stride (floats); 68%4==0 -> float4 aligned

__global__ void flash_attn_kernel(const float* __restrict__ Q,
                                  const float* __restrict__ K,
                                  const float* __restrict__ V,
                                  float* __restrict__ Out) {
    extern __shared__ float sm[];
    float* Qs = sm;                   // [64][FS] transposed: Qs[d*FS + r]
    float* Ks = Qs + 64 * FS;         // [64][FS] transposed: Ks[d*FS + c]
    float* Ps = Ks + 64 * FS;         // [64][FS] : Ps[r*FS + c]
    float* Vs = Ps + 64 * FS;         // [64][64] : Vs[j*64 + dv]

    const int tid = threadIdx.x;
    const int tx = tid & 15;
    const int ty = tid >> 4;
    const int bh = blockIdx.x;        // b*H + h
    const int qt = blockIdx.y;
    const int q0 = qt * 64;

    const float* Qb = Q + (size_t)bh * Sc * DKc;
    const float* Kb = K + (size_t)bh * Sc * DKc;
    const float* Vb = V + (size_t)bh * Sc * DKc;

    // Load Q tile transposed, pre-scaled by 1/sqrt(dk). float4 global reads.
#pragma unroll
    for (int it = 0; it < 4; it++) {
        int e = (tid + it * 256) * 4;
        int r = e >> 6, d = e & 63;
        float4 g = *(const float4*)&Qb[(size_t)(q0 + r) * DKc + d];
        Qs[(d + 0) * FS + r] = g.x * 0.125f;
        Qs[(d + 1) * FS + r] = g.y * 0.125f;
        Qs[(d + 2) * FS + r] = g.z * 0.125f;
        Qs[(d + 3) * FS + r] = g.w * 0.125f;
    }

    float acc[4][4];
#pragma unroll
    for (int i = 0; i < 4; i++)
#pragma unroll
        for (int j = 0; j < 4; j++) acc[i][j] = 0.f;
    float mrow[4], lrow[4];
#pragma unroll
    for (int i = 0; i < 4; i++) { mrow[i] = -INFINITY; lrow[i] = 0.f; }

    const int nkt = qt + 1;           // causal tile skipping
    for (int kt = 0; kt < nkt; kt++) {
        const int k0 = kt * 64;

        __syncthreads();   // previous PV reads of Ks/Vs/Ps done
        // K^T tile (transposed store) + V tile (direct), float4 global reads
#pragma unroll
        for (int it = 0; it < 4; it++) {
            int e = (tid + it * 256) * 4;
            int c = e >> 6, d = e & 63;
            float4 g = *(const float4*)&Kb[(size_t)(k0 + c) * DKc + d];
            Ks[(d + 0) * FS + c] = g.x;
            Ks[(d + 1) * FS + c] = g.y;
            Ks[(d + 2) * FS + c] = g.z;
            Ks[(d + 3) * FS + c] = g.w;
            float4 gv = *(const float4*)&Vb[(size_t)(k0 + c) * DKc + d];
            *(float4*)&Vs[c * 64 + d] = gv;
        }
        __syncthreads();

        // S = (Q*scale) @ K^T  — 2 LDS.128 + 16 FFMA per d
        float sreg[4][4];
#pragma unroll
        for (int i = 0; i < 4; i++)
#pragma unroll
            for (int j = 0; j < 4; j++) sreg[i][j] = 0.f;

#pragma unroll
        for (int d = 0; d < 64; d++) {
            float4 av = *(const float4*)&Qs[d * FS + ty * 4];
            float4 bv = *(const float4*)&Ks[d * FS + tx * 4];
            float a[4] = {av.x, av.y, av.z, av.w};
            float bb[4] = {bv.x, bv.y, bv.z, bv.w};
#pragma unroll
            for (int i = 0; i < 4; i++)
#pragma unroll
                for (int j = 0; j < 4; j++) sreg[i][j] += a[i] * bb[j];
        }

        // Causal mask (diagonal tile only)
        if (kt == qt) {
#pragma unroll
            for (int i = 0; i < 4; i++)
#pragma unroll
                for (int j = 0; j < 4; j++)
                    if (tx * 4 + j > ty * 4 + i) sreg[i][j] = -INFINITY;
        }

        // Register online-softmax: reductions across the 16-lane row group
#pragma unroll
        for (int i = 0; i < 4; i++) {
            float mx = fmaxf(fmaxf(sreg[i][0], sreg[i][1]),
                             fmaxf(sreg[i][2], sreg[i][3]));
#pragma unroll
            for (int off = 8; off >= 1; off >>= 1)
                mx = fmaxf(mx, __shfl_xor_sync(0xffffffffu, mx, off, 16));
            float mnew = fmaxf(mrow[i], mx);
            float cr = __expf(mrow[i] - mnew);      // 0 on first tile
            float sum = 0.f;
#pragma unroll
            for (int j = 0; j < 4; j++) {
                float p = __expf(sreg[i][j] - mnew);
                sreg[i][j] = p;
                sum += p;
            }
#pragma unroll
            for (int off = 8; off >= 1; off >>= 1)
                sum += __shfl_xor_sync(0xffffffffu, sum, off, 16);
            lrow[i] = lrow[i] * cr + sum;
            mrow[i] = mnew;
#pragma unroll
            for (int x = 0; x < 4; x++) acc[i][x] *= cr;
        }

        // Publish P
#pragma unroll
        for (int i = 0; i < 4; i++)
            *(float4*)&Ps[(ty * 4 + i) * FS + tx * 4] =
                make_float4(sreg[i][0], sreg[i][1], sreg[i][2], sreg[i][3]);
        __syncthreads();

        // acc += P @ V  — 8 LDS.128 + 64 FFMA per 4-col chunk of j
#pragma unroll 4
        for (int j0 = 0; j0 < 64; j0 += 4) {
            float bv[4][4];
#pragma unroll
            for (int jj = 0; jj < 4; jj++) {
                float4 t = *(const float4*)&Vs[(j0 + jj) * 64 + tx * 4];
                bv[jj][0] = t.x; bv[jj][1] = t.y; bv[jj][2] = t.z; bv[jj][3] = t.w;
            }
#pragma unroll
            for (int i = 0; i < 4; i++) {
                float4 at = *(const float4*)&Ps[(ty * 4 + i) * FS + j0];
                float a[4] = {at.x, at.y, at.z, at.w};
#pragma unroll
                for (int jj = 0; jj < 4; jj++)
#pragma unroll
                    for (int x = 0; x < 4; x++)
                        acc[i][x] += a[jj] * bv[jj][x];
            }
        }
    }

    // Normalize and write out as [B,S,H*DK], float4 stores
    const int b = bh >> 4;
    const int h = bh & 15;
#pragma unroll
    for (int i = 0; i < 4; i++) {
        float inv = 1.0f / lrow[i];
        float4 o = make_float4(acc[i][0] * inv, acc[i][1] * inv,
                               acc[i][2] * inv, acc[i][3] * inv);
        *(float4*)&Out[(size_t)(b * Sc + q0 + ty * 4 + i) * Dc + h * DKc + tx * 4] = o;
    }
}

// ---------------------------------------------------------------------------
extern "C" void kernel_launch(void* const* d_in, const int* in_sizes, int n_in,
                              void* d_out, int out_size) {
    const float* x    = (const float*)d_in[0];   // [B,S,D]
    const float* Wqkv = (const float*)d_in[1];   // [D, 3D]
    const float* Wo   = (const float*)d_in[2];   // [D, D]
    float* out = (float*)d_out;

    float *qkv, *q, *k, *v, *attn;
    cudaGetSymbolAddress((void**)&qkv,  g_qkv);
    cudaGetSymbolAddress((void**)&q,    g_q);
    cudaGetSymbolAddress((void**)&k,    g_k);
    cudaGetSymbolAddress((void**)&v,    g_v);
    cudaGetSymbolAddress((void**)&attn, g_attn);

    // 1. QKV projection: [4096,1024] @ [1024,3072]
    sgemm_kernel<<<dim3(3 * Dc / 128, BSc / 128), 256>>>(x, Wqkv, qkv, BSc, 3 * Dc, Dc);

    // 2. RoPE + head split
    rope_split_kernel<<<(Bc * Sc * Hc * DKc) / 256, 256>>>(qkv, q, k, v);

    // 3. Causal flash attention
    const int smem = (64 * FS * 3 + 64 * 64) * (int)sizeof(float);  // 68608 B
    cudaFuncSetAttribute(flash_attn_kernel,
                         cudaFuncAttributeMaxDynamicSharedMemorySize, smem);
    flash_attn_kernel<<<dim3(Bc * Hc, Sc / 64), 256, smem>>>(q, k, v, attn);

    // 4. Output projection: [4096,1024] @ [1024,1024]
    sgemm_kernel<<<dim3(Dc / 128, BSc / 128), 256>>>(attn, Wo, out, BSc, Dc, Dc);
}

// round 5
// speedup vs baseline: 1.2480x; 1.1928x over previous
#include <cuda_runtime.h>
#include <math.h>

#define Bc 2
#define Sc 2048
#define Dc 1024
#define Hc 16
#define DKc 64
#define BSc (Bc*Sc)   // 4096

// Scratch (no allocations allowed)
__device__ float g_qkv[(size_t)BSc * 3 * Dc];      // [B,S,3,H,DK]
__device__ float g_q[(size_t)Bc*Hc*Sc*DKc];        // [B,H,S,DK]
__device__ float g_k[(size_t)Bc*Hc*Sc*DKc];
__device__ float g_v[(size_t)Bc*Hc*Sc*DKc];
__device__ float g_attn[(size_t)BSc * Dc];         // [B,S,D]

// ---------------------------------------------------------------------------
// Classic 128x128x8 SGEMM, 256 threads, 8x8 per thread. (unchanged)
// ---------------------------------------------------------------------------
__global__ void sgemm_kernel(const float* __restrict__ A,
                             const float* __restrict__ Bm,
                             float* __restrict__ C,
                             int M, int N, int K) {
    __shared__ float As[8 * 132];
    __shared__ float Bs[8 * 128];

    const int tid = threadIdx.x;
    const int tx = tid & 15;
    const int ty = tid >> 4;
    const int m0 = blockIdx.y << 7;
    const int n0 = blockIdx.x << 7;

    float acc[8][8];
#pragma unroll
    for (int i = 0; i < 8; i++)
#pragma unroll
        for (int j = 0; j < 8; j++) acc[i][j] = 0.f;

    for (int k0 = 0; k0 < K; k0 += 8) {
#pragma unroll
        for (int i = 0; i < 4; i++) {
            int e = tid + (i << 8);
            int m = e >> 3, kk = e & 7;
            As[kk * 132 + m] = A[(size_t)(m0 + m) * K + k0 + kk];
        }
#pragma unroll
        for (int i = 0; i < 4; i++) {
            int e = tid + (i << 8);
            int kk = e >> 7, n = e & 127;
            Bs[kk * 128 + n] = Bm[(size_t)(k0 + kk) * N + n0 + n];
        }
        __syncthreads();

#pragma unroll
        for (int kk = 0; kk < 8; kk++) {
            float a[8], bb[8];
#pragma unroll
            for (int i = 0; i < 8; i++) a[i] = As[kk * 132 + ty * 8 + i];
#pragma unroll
            for (int j = 0; j < 8; j++) bb[j] = Bs[kk * 128 + tx * 8 + j];
#pragma unroll
            for (int i = 0; i < 8; i++)
#pragma unroll
                for (int j = 0; j < 8; j++) acc[i][j] += a[i] * bb[j];
        }
        __syncthreads();
    }

#pragma unroll
    for (int i = 0; i < 8; i++)
#pragma unroll
        for (int j = 0; j < 8; j++)
            C[(size_t)(m0 + ty * 8 + i) * N + n0 + tx * 8 + j] = acc[i][j];
}

// ---------------------------------------------------------------------------
// RoPE + split heads (unchanged)
// ---------------------------------------------------------------------------
__global__ void rope_split_kernel(const float* __restrict__ qkv,
                                  float* __restrict__ Q,
                                  float* __restrict__ Kp,
                                  float* __restrict__ V) {
    int idx = blockIdx.x * blockDim.x + threadIdx.x;  // [b][s][h][d]
    int d = idx & 63;
    int h = (idx >> 6) & (Hc - 1);
    int s = (idx >> 10) & (Sc - 1);
    int b = idx >> 21;

    const float* base = qkv + (size_t)(b * Sc + s) * 3 * Dc + h * DKc;
    float qv = base[d];
    float kv = base[Dc + d];
    float vv = base[2 * Dc + d];

    int d2 = d & 31;
    float invf = 1.0f / powf(10000.0f, (float)d2 * (1.0f / 32.0f));
    float ang = (float)s * invf;
    float sn, c;
    sincosf(ang, &sn, &c);

    int dp = d ^ 32;            // rotate_half partner
    float qp = base[dp];
    float kp = base[Dc + dp];
    float sgn = (d < 32) ? -1.0f : 1.0f;

    float qo = qv * c + sgn * qp * sn;
    float ko = kv * c + sgn * kp * sn;

    size_t o = ((size_t)(b * Hc + h) * Sc + s) * DKc + d;
    Q[o] = qo;
    Kp[o] = ko;
    V[o] = vv;
}

// ---------------------------------------------------------------------------
// Flash attention v3: tf32 mma.sync (m16n8k8). 4 warps, Br=Bc=64.
// Warp w owns q-rows [w*16, w*16+16). S and O live in mma C-fragments.
// ---------------------------------------------------------------------------
#define QS 68   // Qs/Ps row stride (words) — conflict-free for A-fragments
#define KS 72   // Kt/Vs row stride (words) — conflict-free for B-fragments

__device__ __forceinline__ unsigned f2tf(float x) {
    unsigned r;
    asm("cvt.rna.tf32.f32 %0, %1;" : "=r"(r) : "f"(x));
    return r;
}

__device__ __forceinline__ void mma8(float4& d, const unsigned a[4],
                                     const unsigned b[2]) {
    asm volatile(
        "mma.sync.aligned.m16n8k8.row.col.f32.tf32.tf32.f32 "
        "{%0,%1,%2,%3}, {%4,%5,%6,%7}, {%8,%9}, {%0,%1,%2,%3};\n"
        : "+f"(d.x), "+f"(d.y), "+f"(d.z), "+f"(d.w)
        : "r"(a[0]), "r"(a[1]), "r"(a[2]), "r"(a[3]), "r"(b[0]), "r"(b[1]));
}

__global__ void flash_attn_kernel(const float* __restrict__ Q,
                                  const float* __restrict__ K,
                                  const float* __restrict__ V,
                                  float* __restrict__ Out) {
    extern __shared__ unsigned smu[];
    unsigned* Qs = smu;               // [64][QS]  tf32, row=q-row, col=d
    unsigned* Ps = Qs + 64 * QS;      // [64][QS]  tf32, row=q-row, col=j
    unsigned* Kt = Ps + 64 * QS;      // [64][KS]  tf32, row=d,    col=key
    unsigned* Vs = Kt + 64 * KS;      // [64][KS]  tf32, row=j,    col=dv

    const int tid = threadIdx.x;      // 128 threads
    const int lane = tid & 31;
    const int w = tid >> 5;           // warp 0..3
    const int g = lane >> 2;          // group id (row within fragment)
    const int tig = lane & 3;         // thread-in-group
    const int w16 = w * 16;

    const int bh = blockIdx.x;        // b*H + h
    const int qt = blockIdx.y;
    const int q0 = qt * 64;

    const float* Qb = Q + (size_t)bh * Sc * DKc;
    const float* Kb = K + (size_t)bh * Sc * DKc;
    const float* Vb = V + (size_t)bh * Sc * DKc;

    // Load Q tile -> tf32 smem (pre-scaled by 1/sqrt(dk))
#pragma unroll
    for (int it = 0; it < 8; it++) {
        int e = (tid + it * 128) * 4;
        int r = e >> 6, d = e & 63;
        float4 q4 = *(const float4*)&Qb[(size_t)(q0 + r) * DKc + d];
        uint4 u;
        u.x = f2tf(q4.x * 0.125f);
        u.y = f2tf(q4.y * 0.125f);
        u.z = f2tf(q4.z * 0.125f);
        u.w = f2tf(q4.w * 0.125f);
        *(uint4*)&Qs[r * QS + d] = u;
    }

    float4 s[8], o[8];
#pragma unroll
    for (int t = 0; t < 8; t++) o[t] = make_float4(0.f, 0.f, 0.f, 0.f);
    float mrow0 = -INFINITY, mrow1 = -INFINITY, lrow0 = 0.f, lrow1 = 0.f;

    const int nkt = qt + 1;           // causal tile skipping
    for (int kt = 0; kt < nkt; kt++) {
        const int k0 = kt * 64;

        __syncthreads();   // prior PV reads of Vs done; prior QK reads of Kt done
        // Load K^T and V tiles as tf32
#pragma unroll
        for (int it = 0; it < 8; it++) {
            int e = (tid + it * 128) * 4;
            int c = e >> 6, d = e & 63;
            float4 k4 = *(const float4*)&Kb[(size_t)(k0 + c) * DKc + d];
            Kt[(d + 0) * KS + c] = f2tf(k4.x);
            Kt[(d + 1) * KS + c] = f2tf(k4.y);
            Kt[(d + 2) * KS + c] = f2tf(k4.z);
            Kt[(d + 3) * KS + c] = f2tf(k4.w);
            float4 v4 = *(const float4*)&Vb[(size_t)(k0 + c) * DKc + d];
            uint4 u;
            u.x = f2tf(v4.x); u.y = f2tf(v4.y);
            u.z = f2tf(v4.z); u.w = f2tf(v4.w);
            *(uint4*)&Vs[c * KS + d] = u;
        }
        __syncthreads();

        // S = (Q*scale) @ K^T : 8 k-steps x 8 n-tiles of m16n8k8
#pragma unroll
        for (int t = 0; t < 8; t++) s[t] = make_float4(0.f, 0.f, 0.f, 0.f);
#pragma unroll
        for (int ks = 0; ks < 8; ks++) {
            const int kk = ks * 8;
            unsigned a[4];
            a[0] = Qs[(w16 + g) * QS + kk + tig];
            a[1] = Qs[(w16 + g + 8) * QS + kk + tig];
            a[2] = Qs[(w16 + g) * QS + kk + tig + 4];
            a[3] = Qs[(w16 + g + 8) * QS + kk + tig + 4];
#pragma unroll
            for (int t = 0; t < 8; t++) {
                unsigned b[2];
                b[0] = Kt[(kk + tig) * KS + t * 8 + g];
                b[1] = Kt[(kk + tig + 4) * KS + t * 8 + g];
                mma8(s[t], a, b);
            }
        }

        // Causal mask (diagonal tile only). Lane rows: g and g+8 (+w16).
        if (kt == qt) {
            const int r0 = q0 + w16 + g;
            const int r1 = r0 + 8;
#pragma unroll
            for (int t = 0; t < 8; t++) {
                int c0 = k0 + t * 8 + 2 * tig;
                if (c0 > r0)     s[t].x = -INFINITY;
                if (c0 + 1 > r0) s[t].y = -INFINITY;
                if (c0 > r1)     s[t].z = -INFINITY;
                if (c0 + 1 > r1) s[t].w = -INFINITY;
            }
        }

        // Online softmax on fragments. Quad (lanes l^1,l^2) shares a row.
        float mx0 = -INFINITY, mx1 = -INFINITY;
#pragma unroll
        for (int t = 0; t < 8; t++) {
            mx0 = fmaxf(mx0, fmaxf(s[t].x, s[t].y));
            mx1 = fmaxf(mx1, fmaxf(s[t].z, s[t].w));
        }
        mx0 = fmaxf(mx0, __shfl_xor_sync(0xffffffffu, mx0, 1));
        mx0 = fmaxf(mx0, __shfl_xor_sync(0xffffffffu, mx0, 2));
        mx1 = fmaxf(mx1, __shfl_xor_sync(0xffffffffu, mx1, 1));
        mx1 = fmaxf(mx1, __shfl_xor_sync(0xffffffffu, mx1, 2));
        float mnew0 = fmaxf(mrow0, mx0);
        float mnew1 = fmaxf(mrow1, mx1);
        float cr0 = __expf(mrow0 - mnew0);
        float cr1 = __expf(mrow1 - mnew1);
        float sum0 = 0.f, sum1 = 0.f;
#pragma unroll
        for (int t = 0; t < 8; t++) {
            s[t].x = __expf(s[t].x - mnew0);
            s[t].y = __expf(s[t].y - mnew0);
            s[t].z = __expf(s[t].z - mnew1);
            s[t].w = __expf(s[t].w - mnew1);
            sum0 += s[t].x + s[t].y;
            sum1 += s[t].z + s[t].w;
        }
        sum0 += __shfl_xor_sync(0xffffffffu, sum0, 1);
        sum0 += __shfl_xor_sync(0xffffffffu, sum0, 2);
        sum1 += __shfl_xor_sync(0xffffffffu, sum1, 1);
        sum1 += __shfl_xor_sync(0xffffffffu, sum1, 2);
        lrow0 = lrow0 * cr0 + sum0;
        lrow1 = lrow1 * cr1 + sum1;
        mrow0 = mnew0;
        mrow1 = mnew1;
#pragma unroll
        for (int t = 0; t < 8; t++) {
            o[t].x *= cr0; o[t].y *= cr0;
            o[t].z *= cr1; o[t].w *= cr1;
        }

        // Publish P as tf32 (C-fragment -> smem -> A-fragment reshape)
#pragma unroll
        for (int t = 0; t < 8; t++) {
            uint2 p0, p1;
            p0.x = f2tf(s[t].x); p0.y = f2tf(s[t].y);
            p1.x = f2tf(s[t].z); p1.y = f2tf(s[t].w);
            *(uint2*)&Ps[(w16 + g) * QS + t * 8 + 2 * tig] = p0;
            *(uint2*)&Ps[(w16 + g + 8) * QS + t * 8 + 2 * tig] = p1;
        }
        __syncthreads();

        // O += P @ V : 8 j-steps x 8 dv-tiles
#pragma unroll
        for (int js = 0; js < 8; js++) {
            const int j0 = js * 8;
            unsigned a[4];
            a[0] = Ps[(w16 + g) * QS + j0 + tig];
            a[1] = Ps[(w16 + g + 8) * QS + j0 + tig];
            a[2] = Ps[(w16 + g) * QS + j0 + tig + 4];
            a[3] = Ps[(w16 + g + 8) * QS + j0 + tig + 4];
#pragma unroll
            for (int t = 0; t < 8; t++) {
                unsigned b[2];
                b[0] = Vs[(j0 + tig) * KS + t * 8 + g];
                b[1] = Vs[(j0 + tig + 4) * KS + t * 8 + g];
                mma8(o[t], a, b);
            }
        }
    }

    // Normalize and write out as [B,S,H*DK]
    const int b = bh >> 4;
    const int h = bh & 15;
    const float inv0 = 1.0f / lrow0;
    const float inv1 = 1.0f / lrow1;
    const size_t row0 = (size_t)(b * Sc + q0 + w16 + g) * Dc + h * DKc;
    const size_t row1 = row0 + 8 * Dc;
#pragma unroll
    for (int t = 0; t < 8; t++) {
        *(float2*)&Out[row0 + t * 8 + 2 * tig] =
            make_float2(o[t].x * inv0, o[t].y * inv0);
        *(float2*)&Out[row1 + t * 8 + 2 * tig] =
            make_float2(o[t].z * inv1, o[t].w * inv1);
    }
}

// ---------------------------------------------------------------------------
extern "C" void kernel_launch(void* const* d_in, const int* in_sizes, int n_in,
                              void* d_out, int out_size) {
    const float* x    = (const float*)d_in[0];   // [B,S,D]
    const float* Wqkv = (const float*)d_in[1];   // [D, 3D]
    const float* Wo   = (const float*)d_in[2];   // [D, D]
    float* out = (float*)d_out;

    float *qkv, *q, *k, *v, *attn;
    cudaGetSymbolAddress((void**)&qkv,  g_qkv);
    cudaGetSymbolAddress((void**)&q,    g_q);
    cudaGetSymbolAddress((void**)&k,    g_k);
    cudaGetSymbolAddress((void**)&v,    g_v);
    cudaGetSymbolAddress((void**)&attn, g_attn);

    // 1. QKV projection: [4096,1024] @ [1024,3072]
    sgemm_kernel<<<dim3(3 * Dc / 128, BSc / 128), 256>>>(x, Wqkv, qkv, BSc, 3 * Dc, Dc);

    // 2. RoPE + head split
    rope_split_kernel<<<(Bc * Sc * Hc * DKc) / 256, 256>>>(qkv, q, k, v);

    // 3. Causal flash attention (tf32 tensor cores)
    const int smem = (64 * QS * 2 + 64 * KS * 2) * (int)sizeof(unsigned);  // 71680 B
    cudaFuncSetAttribute(flash_attn_kernel,
                         cudaFuncAttributeMaxDynamicSharedMemorySize, smem);
    flash_attn_kernel<<<dim3(Bc * Hc, Sc / 64), 128, smem>>>(q, k, v, attn);

    // 4. Output projection: [4096,1024] @ [1024,1024]
    sgemm_kernel<<<dim3(Dc / 128, BSc / 128), 256>>>(attn, Wo, out, BSc, Dc, Dc);
}

// round 6
// speedup vs baseline: 1.3398x; 1.0736x over previous
#include <cuda_runtime.h>
#include <math.h>

#define Bc 2
#define Sc 2048
#define Dc 1024
#define Hc 16
#define DKc 64
#define BSc (Bc*Sc)   // 4096

// Scratch (no allocations allowed)
__device__ float g_qkv[(size_t)BSc * 3 * Dc];      // [B,S,3,H,DK]
__device__ float g_q[(size_t)Bc*Hc*Sc*DKc];        // [B,H,S,DK]
__device__ float g_k[(size_t)Bc*Hc*Sc*DKc];
__device__ float g_v[(size_t)Bc*Hc*Sc*DKc];
__device__ float g_attn[(size_t)BSc * Dc];         // [B,S,D]

// ---------------------------------------------------------------------------
// Classic 128x128x8 SGEMM, 256 threads, 8x8 per thread. (unchanged)
// ---------------------------------------------------------------------------
__global__ void sgemm_kernel(const float* __restrict__ A,
                             const float* __restrict__ Bm,
                             float* __restrict__ C,
                             int M, int N, int K) {
    __shared__ float As[8 * 132];
    __shared__ float Bs[8 * 128];

    const int tid = threadIdx.x;
    const int tx = tid & 15;
    const int ty = tid >> 4;
    const int m0 = blockIdx.y << 7;
    const int n0 = blockIdx.x << 7;

    float acc[8][8];
#pragma unroll
    for (int i = 0; i < 8; i++)
#pragma unroll
        for (int j = 0; j < 8; j++) acc[i][j] = 0.f;

    for (int k0 = 0; k0 < K; k0 += 8) {
#pragma unroll
        for (int i = 0; i < 4; i++) {
            int e = tid + (i << 8);
            int m = e >> 3, kk = e & 7;
            As[kk * 132 + m] = A[(size_t)(m0 + m) * K + k0 + kk];
        }
#pragma unroll
        for (int i = 0; i < 4; i++) {
            int e = tid + (i << 8);
            int kk = e >> 7, n = e & 127;
            Bs[kk * 128 + n] = Bm[(size_t)(k0 + kk) * N + n0 + n];
        }
        __syncthreads();

#pragma unroll
        for (int kk = 0; kk < 8; kk++) {
            float a[8], bb[8];
#pragma unroll
            for (int i = 0; i < 8; i++) a[i] = As[kk * 132 + ty * 8 + i];
#pragma unroll
            for (int j = 0; j < 8; j++) bb[j] = Bs[kk * 128 + tx * 8 + j];
#pragma unroll
            for (int i = 0; i < 8; i++)
#pragma unroll
                for (int j = 0; j < 8; j++) acc[i][j] += a[i] * bb[j];
        }
        __syncthreads();
    }

#pragma unroll
    for (int i = 0; i < 8; i++)
#pragma unroll
        for (int j = 0; j < 8; j++)
            C[(size_t)(m0 + ty * 8 + i) * N + n0 + tx * 8 + j] = acc[i][j];
}

// ---------------------------------------------------------------------------
// RoPE + split heads (unchanged)
// ---------------------------------------------------------------------------
__global__ void rope_split_kernel(const float* __restrict__ qkv,
                                  float* __restrict__ Q,
                                  float* __restrict__ Kp,
                                  float* __restrict__ V) {
    int idx = blockIdx.x * blockDim.x + threadIdx.x;  // [b][s][h][d]
    int d = idx & 63;
    int h = (idx >> 6) & (Hc - 1);
    int s = (idx >> 10) & (Sc - 1);
    int b = idx >> 21;

    const float* base = qkv + (size_t)(b * Sc + s) * 3 * Dc + h * DKc;
    float qv = base[d];
    float kv = base[Dc + d];
    float vv = base[2 * Dc + d];

    int d2 = d & 31;
    float invf = 1.0f / powf(10000.0f, (float)d2 * (1.0f / 32.0f));
    float ang = (float)s * invf;
    float sn, c;
    sincosf(ang, &sn, &c);

    int dp = d ^ 32;            // rotate_half partner
    float qp = base[dp];
    float kp = base[Dc + dp];
    float sgn = (d < 32) ? -1.0f : 1.0f;

    float qo = qv * c + sgn * qp * sn;
    float ko = kv * c + sgn * kp * sn;

    size_t o = ((size_t)(b * Hc + h) * Sc + s) * DKc + d;
    Q[o] = qo;
    Kp[o] = ko;
    V[o] = vv;
}

// ---------------------------------------------------------------------------
// Flash attention v4: tf32 mma.sync, Br=128, Bc=64, 8 warps / 256 threads.
// Warp w owns q-rows [w*16, w*16+16) of the 128-row tile.
// Heavy-first 1D grid: qt descending so 32-k-tile CTAs launch in wave 0.
// ---------------------------------------------------------------------------
#define QS 68   // Qs/Ps row stride (words)
#define KS 72   // Kt/Vs row stride (words)
#define QTILES (Sc / 128)   // 16

__device__ __forceinline__ unsigned f2tf(float x) {
    unsigned r;
    asm("cvt.rna.tf32.f32 %0, %1;" : "=r"(r) : "f"(x));
    return r;
}

__device__ __forceinline__ void mma8(float4& d, const unsigned a[4],
                                     const unsigned b[2]) {
    asm volatile(
        "mma.sync.aligned.m16n8k8.row.col.f32.tf32.tf32.f32 "
        "{%0,%1,%2,%3}, {%4,%5,%6,%7}, {%8,%9}, {%0,%1,%2,%3};\n"
        : "+f"(d.x), "+f"(d.y), "+f"(d.z), "+f"(d.w)
        : "r"(a[0]), "r"(a[1]), "r"(a[2]), "r"(a[3]), "r"(b[0]), "r"(b[1]));
}

__global__ __launch_bounds__(256, 2)
void flash_attn_kernel(const float* __restrict__ Q,
                       const float* __restrict__ K,
                       const float* __restrict__ V,
                       float* __restrict__ Out) {
    extern __shared__ unsigned smu[];
    unsigned* Qs = smu;               // [128][QS] tf32, row=q-row, col=d
    unsigned* Ps = Qs + 128 * QS;     // [128][QS] tf32, row=q-row, col=j
    unsigned* Kt = Ps + 128 * QS;     // [64][KS]  tf32, row=d,    col=key
    unsigned* Vs = Kt + 64 * KS;      // [64][KS]  tf32, row=j,    col=dv

    const int tid = threadIdx.x;      // 256 threads
    const int lane = tid & 31;
    const int w = tid >> 5;           // warp 0..7
    const int g = lane >> 2;
    const int tig = lane & 3;
    const int w16 = w * 16;

    // Heavy-first scheduling: qt descending with blockIdx.x
    const int id = blockIdx.x;
    const int bh = id & 31;                 // b*H + h
    const int qt = (QTILES - 1) - (id >> 5);
    const int q0 = qt * 128;

    const float* Qb = Q + (size_t)bh * Sc * DKc;
    const float* Kb = K + (size_t)bh * Sc * DKc;
    const float* Vb = V + (size_t)bh * Sc * DKc;

    // Load Q tile (128 x 64) -> tf32 smem, pre-scaled by 1/sqrt(dk)
#pragma unroll
    for (int it = 0; it < 8; it++) {
        int e = (tid + it * 256) * 4;
        int r = e >> 6, d = e & 63;
        float4 q4 = *(const float4*)&Qb[(size_t)(q0 + r) * DKc + d];
        uint4 u;
        u.x = f2tf(q4.x * 0.125f);
        u.y = f2tf(q4.y * 0.125f);
        u.z = f2tf(q4.z * 0.125f);
        u.w = f2tf(q4.w * 0.125f);
        *(uint4*)&Qs[r * QS + d] = u;
    }

    float4 s[8], o[8];
#pragma unroll
    for (int t = 0; t < 8; t++) o[t] = make_float4(0.f, 0.f, 0.f, 0.f);
    float mrow0 = -INFINITY, mrow1 = -INFINITY, lrow0 = 0.f, lrow1 = 0.f;

    const int nkt = 2 * qt + 2;       // causal: key tiles of 64
    for (int kt = 0; kt < nkt; kt++) {
        const int k0 = kt * 64;

        __syncthreads();   // prior tile's reads of Kt/Vs/Ps done
        // Load K^T and V tiles (64 x 64 each) as tf32
#pragma unroll
        for (int it = 0; it < 4; it++) {
            int e = (tid + it * 256) * 4;
            int c = e >> 6, d = e & 63;
            float4 k4 = *(const float4*)&Kb[(size_t)(k0 + c) * DKc + d];
            Kt[(d + 0) * KS + c] = f2tf(k4.x);
            Kt[(d + 1) * KS + c] = f2tf(k4.y);
            Kt[(d + 2) * KS + c] = f2tf(k4.z);
            Kt[(d + 3) * KS + c] = f2tf(k4.w);
            float4 v4 = *(const float4*)&Vb[(size_t)(k0 + c) * DKc + d];
            uint4 u;
            u.x = f2tf(v4.x); u.y = f2tf(v4.y);
            u.z = f2tf(v4.z); u.w = f2tf(v4.w);
            *(uint4*)&Vs[c * KS + d] = u;
        }
        __syncthreads();

        // S = (Q*scale) @ K^T : 8 k-steps x 8 n-tiles of m16n8k8
#pragma unroll
        for (int t = 0; t < 8; t++) s[t] = make_float4(0.f, 0.f, 0.f, 0.f);
#pragma unroll
        for (int ks = 0; ks < 8; ks++) {
            const int kk = ks * 8;
            unsigned a[4];
            a[0] = Qs[(w16 + g) * QS + kk + tig];
            a[1] = Qs[(w16 + g + 8) * QS + kk + tig];
            a[2] = Qs[(w16 + g) * QS + kk + tig + 4];
            a[3] = Qs[(w16 + g + 8) * QS + kk + tig + 4];
#pragma unroll
            for (int t = 0; t < 8; t++) {
                unsigned b[2];
                b[0] = Kt[(kk + tig) * KS + t * 8 + g];
                b[1] = Kt[(kk + tig + 4) * KS + t * 8 + g];
                mma8(s[t], a, b);
            }
        }

        // Causal mask — needed only on the last two key tiles
        if (kt >= 2 * qt) {
            const int r0 = q0 + w16 + g;
            const int r1 = r0 + 8;
#pragma unroll
            for (int t = 0; t < 8; t++) {
                int c0 = k0 + t * 8 + 2 * tig;
                if (c0 > r0)     s[t].x = -INFINITY;
                if (c0 + 1 > r0) s[t].y = -INFINITY;
                if (c0 > r1)     s[t].z = -INFINITY;
                if (c0 + 1 > r1) s[t].w = -INFINITY;
            }
        }

        // Online softmax on fragments. Quad (lanes l^1,l^2) shares a row.
        float mx0 = -INFINITY, mx1 = -INFINITY;
#pragma unroll
        for (int t = 0; t < 8; t++) {
            mx0 = fmaxf(mx0, fmaxf(s[t].x, s[t].y));
            mx1 = fmaxf(mx1, fmaxf(s[t].z, s[t].w));
        }
        mx0 = fmaxf(mx0, __shfl_xor_sync(0xffffffffu, mx0, 1));
        mx0 = fmaxf(mx0, __shfl_xor_sync(0xffffffffu, mx0, 2));
        mx1 = fmaxf(mx1, __shfl_xor_sync(0xffffffffu, mx1, 1));
        mx1 = fmaxf(mx1, __shfl_xor_sync(0xffffffffu, mx1, 2));
        float mnew0 = fmaxf(mrow0, mx0);
        float mnew1 = fmaxf(mrow1, mx1);
        float cr0 = __expf(mrow0 - mnew0);
        float cr1 = __expf(mrow1 - mnew1);
        float sum0 = 0.f, sum1 = 0.f;
#pragma unroll
        for (int t = 0; t < 8; t++) {
            s[t].x = __expf(s[t].x - mnew0);
            s[t].y = __expf(s[t].y - mnew0);
            s[t].z = __expf(s[t].z - mnew1);
            s[t].w = __expf(s[t].w - mnew1);
            sum0 += s[t].x + s[t].y;
            sum1 += s[t].z + s[t].w;
        }
        sum0 += __shfl_xor_sync(0xffffffffu, sum0, 1);
        sum0 += __shfl_xor_sync(0xffffffffu, sum0, 2);
        sum1 += __shfl_xor_sync(0xffffffffu, sum1, 1);
        sum1 += __shfl_xor_sync(0xffffffffu, sum1, 2);
        lrow0 = lrow0 * cr0 + sum0;
        lrow1 = lrow1 * cr1 + sum1;
        mrow0 = mnew0;
        mrow1 = mnew1;
#pragma unroll
        for (int t = 0; t < 8; t++) {
            o[t].x *= cr0; o[t].y *= cr0;
            o[t].z *= cr1; o[t].w *= cr1;
        }

        // Publish P as tf32 (C-fragment -> smem -> A-fragment reshape)
#pragma unroll
        for (int t = 0; t < 8; t++) {
            uint2 p0, p1;
            p0.x = f2tf(s[t].x); p0.y = f2tf(s[t].y);
            p1.x = f2tf(s[t].z); p1.y = f2tf(s[t].w);
            *(uint2*)&Ps[(w16 + g) * QS + t * 8 + 2 * tig] = p0;
            *(uint2*)&Ps[(w16 + g + 8) * QS + t * 8 + 2 * tig] = p1;
        }
        __syncthreads();

        // O += P @ V : 8 j-steps x 8 dv-tiles
#pragma unroll
        for (int js = 0; js < 8; js++) {
            const int j0 = js * 8;
            unsigned a[4];
            a[0] = Ps[(w16 + g) * QS + j0 + tig];
            a[1] = Ps[(w16 + g + 8) * QS + j0 + tig];
            a[2] = Ps[(w16 + g) * QS + j0 + tig + 4];
            a[3] = Ps[(w16 + g + 8) * QS + j0 + tig + 4];
#pragma unroll
            for (int t = 0; t < 8; t++) {
                unsigned b[2];
                b[0] = Vs[(j0 + tig) * KS + t * 8 + g];
                b[1] = Vs[(j0 + tig + 4) * KS + t * 8 + g];
                mma8(o[t], a, b);
            }
        }
    }

    // Normalize and write out as [B,S,H*DK]
    const int b = bh >> 4;
    const int h = bh & 15;
    const float inv0 = 1.0f / lrow0;
    const float inv1 = 1.0f / lrow1;
    const size_t row0 = (size_t)(b * Sc + q0 + w16 + g) * Dc + h * DKc;
    const size_t row1 = row0 + 8 * Dc;
#pragma unroll
    for (int t = 0; t < 8; t++) {
        *(float2*)&Out[row0 + t * 8 + 2 * tig] =
            make_float2(o[t].x * inv0, o[t].y * inv0);
        *(float2*)&Out[row1 + t * 8 + 2 * tig] =
            make_float2(o[t].z * inv1, o[t].w * inv1);
    }
}

// ---------------------------------------------------------------------------
extern "C" void kernel_launch(void* const* d_in, const int* in_sizes, int n_in,
                              void* d_out, int out_size) {
    const float* x    = (const float*)d_in[0];   // [B,S,D]
    const float* Wqkv = (const float*)d_in[1];   // [D, 3D]
    const float* Wo   = (const float*)d_in[2];   // [D, D]
    float* out = (float*)d_out;

    float *qkv, *q, *k, *v, *attn;
    cudaGetSymbolAddress((void**)&qkv,  g_qkv);
    cudaGetSymbolAddress((void**)&q,    g_q);
    cudaGetSymbolAddress((void**)&k,    g_k);
    cudaGetSymbolAddress((void**)&v,    g_v);
    cudaGetSymbolAddress((void**)&attn, g_attn);

    // 1. QKV projection: [4096,1024] @ [1024,3072]
    sgemm_kernel<<<dim3(3 * Dc / 128, BSc / 128), 256>>>(x, Wqkv, qkv, BSc, 3 * Dc, Dc);

    // 2. RoPE + head split
    rope_split_kernel<<<(Bc * Sc * Hc * DKc) / 256, 256>>>(qkv, q, k, v);

    // 3. Causal flash attention (tf32 tensor cores, Br=128)
    const int smem = (128 * QS * 2 + 64 * KS * 2) * (int)sizeof(unsigned);  // 106496 B
    cudaFuncSetAttribute(flash_attn_kernel,
                         cudaFuncAttributeMaxDynamicSharedMemorySize, smem);
    flash_attn_kernel<<<32 * QTILES, 256, smem>>>(q, k, v, attn);

    // 4. Output projection: [4096,1024] @ [1024,1024]
    sgemm_kernel<<<dim3(Dc / 128, BSc / 128), 256>>>(attn, Wo, out, BSc, Dc, Dc);
}